// round 1
// baseline (speedup 1.0000x reference)
#include <cuda_runtime.h>
#include <cstdint>

// ---------------- scratch (device globals: allocation-free rule) ----------------
__device__ float g_wq[8u * 16u * 1024u * 64u];      // [b,h,i,s]  32 MB
__device__ float g_wk[8u * 16u * 1024u * 64u];      // [b,h,j,s]  32 MB
__device__ float g_wv[8u * 16u * 1024u * 64u];      // [b,h,j,s]  32 MB
__device__ float g_scores[134217728u];              // [b,h,i,j] 512 MB
__device__ float g_heads[8u * 16u * 1024u * 64u];   // [b,h,i,s]  32 MB

// =====================================================================
// Generic 128x128x16 double-buffered FP32 GEMM, 256 threads, 8x8 micro.
// MODE 0: B row-major [K=1024 x N=1024], C row-major ldc=1024  (output proj)
// MODE 1: B is weight [h,q,s] viewed as [K x (h*64+s)], C -> [b,h,i,s] (projections)
// A is always row-major lda=1024, M tiles of 128 (within-batch aligned).
// =====================================================================
template <int MODE>
__global__ __launch_bounds__(256, 2) void gemm128_nn(const float* __restrict__ A,
                                                     const float* __restrict__ B,
                                                     float* __restrict__ C) {
    __shared__ float As[2][16][132];  // transposed: As[k][m]
    __shared__ float Bs[2][16][132];  // Bs[k][n]

    const int t = threadIdx.x;
    const int tx = t & 15;
    const int ty = t >> 4;
    const int m0 = blockIdx.y * 128;
    const int n0 = blockIdx.x * 128;

    const int am = t >> 2;          // 0..63 (two halves: +64)
    const int ak = (t & 3) << 2;    // 0,4,8,12
    const int bk = t >> 5;          // 0..7 (two halves: +8)
    const int bn = (t & 31) << 2;   // 0..124

    float acc[8][8];
#pragma unroll
    for (int i = 0; i < 8; i++)
#pragma unroll
        for (int j = 0; j < 8; j++) acc[i][j] = 0.f;

    float4 a0, a1, b0, b1;

    auto loadAB = [&](int k0) {
        a0 = *(const float4*)(A + (size_t)(m0 + am) * 1024 + k0 + ak);
        a1 = *(const float4*)(A + (size_t)(m0 + am + 64) * 1024 + k0 + ak);
        if (MODE == 0) {
            b0 = *(const float4*)(B + (size_t)(k0 + bk) * 1024 + n0 + bn);
            b1 = *(const float4*)(B + (size_t)(k0 + bk + 8) * 1024 + n0 + bn);
        } else {
            const int n = n0 + bn;
            const size_t base = ((size_t)(n >> 6) << 16) + (size_t)(n & 63);
            b0 = *(const float4*)(B + base + (size_t)(k0 + bk) * 64);
            b1 = *(const float4*)(B + base + (size_t)(k0 + bk + 8) * 64);
        }
    };
    auto stage = [&](int buf) {
        As[buf][ak + 0][am] = a0.x;
        As[buf][ak + 1][am] = a0.y;
        As[buf][ak + 2][am] = a0.z;
        As[buf][ak + 3][am] = a0.w;
        As[buf][ak + 0][am + 64] = a1.x;
        As[buf][ak + 1][am + 64] = a1.y;
        As[buf][ak + 2][am + 64] = a1.z;
        As[buf][ak + 3][am + 64] = a1.w;
        *(float4*)(&Bs[buf][bk][bn]) = b0;
        *(float4*)(&Bs[buf][bk + 8][bn]) = b1;
    };

    loadAB(0);
    stage(0);
    __syncthreads();

    int buf = 0;
#pragma unroll 1
    for (int s = 0; s < 64; s++) {
        if (s + 1 < 64) loadAB((s + 1) << 4);
#pragma unroll
        for (int kk = 0; kk < 16; kk++) {
            float4 x0 = *(const float4*)(&As[buf][kk][ty * 8]);
            float4 x1 = *(const float4*)(&As[buf][kk][ty * 8 + 4]);
            float4 y0 = *(const float4*)(&Bs[buf][kk][tx * 8]);
            float4 y1 = *(const float4*)(&Bs[buf][kk][tx * 8 + 4]);
            float av[8] = {x0.x, x0.y, x0.z, x0.w, x1.x, x1.y, x1.z, x1.w};
            float bv[8] = {y0.x, y0.y, y0.z, y0.w, y1.x, y1.y, y1.z, y1.w};
#pragma unroll
            for (int i = 0; i < 8; i++)
#pragma unroll
                for (int j = 0; j < 8; j++) acc[i][j] = fmaf(av[i], bv[j], acc[i][j]);
        }
        if (s + 1 < 64) stage(buf ^ 1);
        __syncthreads();
        buf ^= 1;
    }

#pragma unroll
    for (int u = 0; u < 8; u++) {
        const int m = m0 + ty * 8 + u;
        float4 c0 = make_float4(acc[u][0], acc[u][1], acc[u][2], acc[u][3]);
        float4 c1 = make_float4(acc[u][4], acc[u][5], acc[u][6], acc[u][7]);
        if (MODE == 0) {
            float* cp = C + (size_t)m * 1024 + n0 + tx * 8;
            *(float4*)cp = c0;
            *(float4*)(cp + 4) = c1;
        } else {
            const int n = n0 + tx * 8;  // 8-wide block never crosses a 64-boundary
            const size_t base = ((size_t)(m >> 10) << 20) + ((size_t)(n >> 6) << 16) +
                                ((size_t)(m & 1023) << 6) + (size_t)(n & 63);
            float* cp = C + base;
            *(float4*)cp = c0;
            *(float4*)(cp + 4) = c1;
        }
    }
}

// =====================================================================
// Scores: per (b,h): S[i,j] = 0.25 * WQ[i,:] . WK[j,:]   (K=64)
// 128x128 tile, BK=16, both operands transposed into smem.
// =====================================================================
__global__ __launch_bounds__(256, 2) void scores_kernel(const float* __restrict__ WQ,
                                                        const float* __restrict__ WK,
                                                        float* __restrict__ S) {
    __shared__ float As[2][16][132];
    __shared__ float Bs[2][16][132];

    const int t = threadIdx.x;
    const int tx = t & 15;
    const int ty = t >> 4;
    const size_t bh = blockIdx.z;
    const float* Aq = WQ + bh * 65536;
    const float* Bk = WK + bh * 65536;
    float* C = S + bh * 1048576;
    const int m0 = blockIdx.y * 128;
    const int n0 = blockIdx.x * 128;

    const int am = t >> 2;
    const int ak = (t & 3) << 2;

    float acc[8][8];
#pragma unroll
    for (int i = 0; i < 8; i++)
#pragma unroll
        for (int j = 0; j < 8; j++) acc[i][j] = 0.f;

    float4 a0, a1, b0, b1;
    auto loadAB = [&](int k0) {
        a0 = *(const float4*)(Aq + (size_t)(m0 + am) * 64 + k0 + ak);
        a1 = *(const float4*)(Aq + (size_t)(m0 + am + 64) * 64 + k0 + ak);
        b0 = *(const float4*)(Bk + (size_t)(n0 + am) * 64 + k0 + ak);
        b1 = *(const float4*)(Bk + (size_t)(n0 + am + 64) * 64 + k0 + ak);
    };
    auto stage = [&](int buf) {
        As[buf][ak + 0][am] = a0.x;
        As[buf][ak + 1][am] = a0.y;
        As[buf][ak + 2][am] = a0.z;
        As[buf][ak + 3][am] = a0.w;
        As[buf][ak + 0][am + 64] = a1.x;
        As[buf][ak + 1][am + 64] = a1.y;
        As[buf][ak + 2][am + 64] = a1.z;
        As[buf][ak + 3][am + 64] = a1.w;
        Bs[buf][ak + 0][am] = b0.x;
        Bs[buf][ak + 1][am] = b0.y;
        Bs[buf][ak + 2][am] = b0.z;
        Bs[buf][ak + 3][am] = b0.w;
        Bs[buf][ak + 0][am + 64] = b1.x;
        Bs[buf][ak + 1][am + 64] = b1.y;
        Bs[buf][ak + 2][am + 64] = b1.z;
        Bs[buf][ak + 3][am + 64] = b1.w;
    };

    loadAB(0);
    stage(0);
    __syncthreads();

    int buf = 0;
#pragma unroll 1
    for (int s = 0; s < 4; s++) {
        if (s + 1 < 4) loadAB((s + 1) << 4);
#pragma unroll
        for (int kk = 0; kk < 16; kk++) {
            float4 x0 = *(const float4*)(&As[buf][kk][ty * 8]);
            float4 x1 = *(const float4*)(&As[buf][kk][ty * 8 + 4]);
            float4 y0 = *(const float4*)(&Bs[buf][kk][tx * 8]);
            float4 y1 = *(const float4*)(&Bs[buf][kk][tx * 8 + 4]);
            float av[8] = {x0.x, x0.y, x0.z, x0.w, x1.x, x1.y, x1.z, x1.w};
            float bv[8] = {y0.x, y0.y, y0.z, y0.w, y1.x, y1.y, y1.z, y1.w};
#pragma unroll
            for (int i = 0; i < 8; i++)
#pragma unroll
                for (int j = 0; j < 8; j++) acc[i][j] = fmaf(av[i], bv[j], acc[i][j]);
        }
        if (s + 1 < 4) stage(buf ^ 1);
        __syncthreads();
        buf ^= 1;
    }

#pragma unroll
    for (int u = 0; u < 8; u++) {
        float* cp = C + (size_t)(m0 + ty * 8 + u) * 1024 + n0 + tx * 8;
        *(float4*)cp = make_float4(0.25f * acc[u][0], 0.25f * acc[u][1],
                                   0.25f * acc[u][2], 0.25f * acc[u][3]);
        *(float4*)(cp + 4) = make_float4(0.25f * acc[u][4], 0.25f * acc[u][5],
                                         0.25f * acc[u][6], 0.25f * acc[u][7]);
    }
}

// =====================================================================
// Softmax over the batch axis: w[b,h,i,j] = softmax_b(S[:,h,i,j])
// One thread handles 4 consecutive j for all 8 batches.
// =====================================================================
__global__ void softmax_b(float* __restrict__ S) {
    const size_t idx = ((size_t)blockIdx.x * 256 + threadIdx.x) * 4;
    float v[8][4];
#pragma unroll
    for (int b = 0; b < 8; b++) {
        float4 x = *(const float4*)(S + (size_t)b * 16777216u + idx);
        v[b][0] = x.x; v[b][1] = x.y; v[b][2] = x.z; v[b][3] = x.w;
    }
#pragma unroll
    for (int c = 0; c < 4; c++) {
        float mx = v[0][c];
#pragma unroll
        for (int b = 1; b < 8; b++) mx = fmaxf(mx, v[b][c]);
        float sum = 0.f;
#pragma unroll
        for (int b = 0; b < 8; b++) {
            v[b][c] = __expf(v[b][c] - mx);
            sum += v[b][c];
        }
        const float inv = 1.0f / sum;
#pragma unroll
        for (int b = 0; b < 8; b++) v[b][c] *= inv;
    }
#pragma unroll
    for (int b = 0; b < 8; b++) {
        *(float4*)(S + (size_t)b * 16777216u + idx) =
            make_float4(v[b][0], v[b][1], v[b][2], v[b][3]);
    }
}

// =====================================================================
// PV: per (b,h): heads[i,s] = sum_j P[i,j] * WV[j,s]    (M=1024,N=64,K=1024)
// 128x64 tile, BK=16, 256 threads, 8x4 micro.
// =====================================================================
__global__ __launch_bounds__(256, 2) void pv_kernel(const float* __restrict__ P,
                                                    const float* __restrict__ WV,
                                                    float* __restrict__ O) {
    __shared__ float As[2][16][132];  // transposed P tile
    __shared__ float Bs[2][16][68];   // WV tile [k][s]

    const int t = threadIdx.x;
    const int tx = t & 15;
    const int ty = t >> 4;
    const size_t bh = blockIdx.z;
    const float* A = P + bh * 1048576;
    const float* B = WV + bh * 65536;
    float* C = O + bh * 65536;
    const int m0 = blockIdx.y * 128;

    const int am = t >> 2;
    const int ak = (t & 3) << 2;
    const int bk = t >> 4;          // 0..15
    const int bn = (t & 15) << 2;   // 0..60

    float acc[8][4];
#pragma unroll
    for (int i = 0; i < 8; i++)
#pragma unroll
        for (int j = 0; j < 4; j++) acc[i][j] = 0.f;

    float4 a0, a1, b0;
    auto loadAB = [&](int k0) {
        a0 = *(const float4*)(A + (size_t)(m0 + am) * 1024 + k0 + ak);
        a1 = *(const float4*)(A + (size_t)(m0 + am + 64) * 1024 + k0 + ak);
        b0 = *(const float4*)(B + (size_t)(k0 + bk) * 64 + bn);
    };
    auto stage = [&](int buf) {
        As[buf][ak + 0][am] = a0.x;
        As[buf][ak + 1][am] = a0.y;
        As[buf][ak + 2][am] = a0.z;
        As[buf][ak + 3][am] = a0.w;
        As[buf][ak + 0][am + 64] = a1.x;
        As[buf][ak + 1][am + 64] = a1.y;
        As[buf][ak + 2][am + 64] = a1.z;
        As[buf][ak + 3][am + 64] = a1.w;
        *(float4*)(&Bs[buf][bk][bn]) = b0;
    };

    loadAB(0);
    stage(0);
    __syncthreads();

    int buf = 0;
#pragma unroll 1
    for (int s = 0; s < 64; s++) {
        if (s + 1 < 64) loadAB((s + 1) << 4);
#pragma unroll
        for (int kk = 0; kk < 16; kk++) {
            float4 x0 = *(const float4*)(&As[buf][kk][ty * 8]);
            float4 x1 = *(const float4*)(&As[buf][kk][ty * 8 + 4]);
            float4 y0 = *(const float4*)(&Bs[buf][kk][tx * 4]);
            float av[8] = {x0.x, x0.y, x0.z, x0.w, x1.x, x1.y, x1.z, x1.w};
            float bv[4] = {y0.x, y0.y, y0.z, y0.w};
#pragma unroll
            for (int i = 0; i < 8; i++)
#pragma unroll
                for (int j = 0; j < 4; j++) acc[i][j] = fmaf(av[i], bv[j], acc[i][j]);
        }
        if (s + 1 < 64) stage(buf ^ 1);
        __syncthreads();
        buf ^= 1;
    }

#pragma unroll
    for (int u = 0; u < 8; u++) {
        float* cp = C + (size_t)(m0 + ty * 8 + u) * 64 + tx * 4;
        *(float4*)cp = make_float4(acc[u][0], acc[u][1], acc[u][2], acc[u][3]);
    }
}

// =====================================================================
// launcher
// =====================================================================
extern "C" void kernel_launch(void* const* d_in, const int* in_sizes, int n_in,
                              void* d_out, int out_size) {
    const float* query = (const float*)d_in[0];
    const float* key_ = (const float*)d_in[1];
    const float* value = (const float*)d_in[2];
    const float* q_w = (const float*)d_in[3];
    const float* k_w = (const float*)d_in[4];
    const float* v_w = (const float*)d_in[5];
    const float* o_w = (const float*)d_in[6];
    float* out = (float*)d_out;

    float *wq, *wk, *wv, *sc, *hd;
    cudaGetSymbolAddress((void**)&wq, g_wq);
    cudaGetSymbolAddress((void**)&wk, g_wk);
    cudaGetSymbolAddress((void**)&wv, g_wv);
    cudaGetSymbolAddress((void**)&sc, g_scores);
    cudaGetSymbolAddress((void**)&hd, g_heads);

    // 1) projections: [8192 x 1024] x weights -> [b,h,seq,64]
    gemm128_nn<1><<<dim3(8, 64), 256>>>(query, q_w, wq);
    gemm128_nn<1><<<dim3(8, 64), 256>>>(key_, k_w, wk);
    gemm128_nn<1><<<dim3(8, 64), 256>>>(value, v_w, wv);
    // 2) scores = 0.25 * WQ WK^T per (b,h)
    scores_kernel<<<dim3(8, 8, 128), 256>>>(wq, wk, sc);
    // 3) softmax over batch axis
    softmax_b<<<16384, 256>>>(sc);
    // 4) heads = P * WV per (b,h)  -> contiguous [b,h,i,s] == flat [b,1024,1024]
    pv_kernel<<<dim3(1, 8, 128), 256>>>(sc, wv, hd);
    // 5) out = heads_flat x o_w
    gemm128_nn<0><<<dim3(8, 64), 256>>>(hd, o_w, out);
}

// round 3
// speedup vs baseline: 1.1860x; 1.1860x over previous
#include <cuda_runtime.h>
#include <cstdint>

// ============================ helpers ============================
__device__ __forceinline__ float to_tf32(float x) {
    uint32_t u;
    asm("cvt.rna.tf32.f32 %0, %1;" : "=r"(u) : "f"(x));
    return __uint_as_float(u);
}
__device__ __forceinline__ void mma8(float* c, const uint32_t* a, const uint32_t* b) {
    asm volatile(
        "mma.sync.aligned.m16n8k8.row.col.f32.tf32.tf32.f32 "
        "{%0,%1,%2,%3}, {%4,%5,%6,%7}, {%8,%9}, {%0,%1,%2,%3};"
        : "+f"(c[0]), "+f"(c[1]), "+f"(c[2]), "+f"(c[3])
        : "r"(a[0]), "r"(a[1]), "r"(a[2]), "r"(a[3]), "r"(b[0]), "r"(b[1]));
}

// ============================ device globals ============================
__device__ float g_qh[8388608], g_ql[8388608];    // query split
__device__ float g_kh[8388608], g_kl[8388608];    // key split
__device__ float g_qwh[1048576], g_qwl[1048576];  // q_w split
__device__ float g_kwh[1048576], g_kwl[1048576];  // k_w split
__device__ float g_wqh[8388608], g_wql[8388608];  // projected Q split [b,h,i,s]
__device__ float g_wkh[8388608], g_wkl[8388608];  // projected K split [b,h,j,s]
__device__ float g_wv[8388608];                   // projected V [b,h,j,s]
__device__ float g_scores[134217728];             // [b,h,i,j]
__device__ float g_heads[8388608];                // [b,h,i,s]

// ============================ split kernel ============================
__global__ void split_k(const float* __restrict__ x, float* __restrict__ hi,
                        float* __restrict__ lo) {
    size_t i = ((size_t)blockIdx.x * 256 + threadIdx.x) * 4;
    float4 v = *(const float4*)(x + i);
    float4 h, l;
    h.x = to_tf32(v.x); l.x = to_tf32(v.x - h.x);
    h.y = to_tf32(v.y); l.y = to_tf32(v.y - h.y);
    h.z = to_tf32(v.z); l.z = to_tf32(v.z - h.z);
    h.w = to_tf32(v.w); l.w = to_tf32(v.w - h.w);
    *(float4*)(hi + i) = h;
    *(float4*)(lo + i) = l;
}

// ============================ tf32 mma.sync GEMM ============================
// C[128 x NTILE] = A[128 x KTOT] * op(B), per blockIdx.z slice.
// SPLIT: 3-term hi/lo tf32 emulation (AhBh + AhBl + AlBh).
// BMODE: 0 = B row-major [K x N] (ldb=LDB);  1 = per-head weight [h][k][s];
//        2 = B row-major [N x K] (ldb=LDB)  (i.e. C = A * B^T)
// CMODE: 0 = plain row-major C (+ z*cZ, ldc=LDC), scaled
//        1 = [b,h,i,s] packed layout, split-write hi/lo
//        2 = [b,h,i,s] packed layout, fp32, scaled
template <int KTOT, int NTILE, bool SPLIT, int BMODE, int CMODE, bool RNDA, bool RNDB,
          int LDA, int LDB, int LDC>
__global__ void __launch_bounds__(256) mma_gemm(
    const float* __restrict__ Ah, const float* __restrict__ Al,
    const float* __restrict__ Bh, const float* __restrict__ Bl,
    float* __restrict__ Ch, float* __restrict__ Cl,
    size_t aZ, size_t bZ, size_t cZ, float scale) {
    extern __shared__ float smf[];
    constexpr int LP = 132;           // padded row length
    constexpr int BUF = 16 * LP;      // one k-slab
    float* AsH = smf;                 // [2][16][132]
    float* BsH = smf + 2 * BUF;
    float* AsL = smf + 4 * BUF;       // SPLIT only
    float* BsL = smf + 6 * BUF;

    const int t = threadIdx.x;
    const int lane = t & 31, wid = t >> 5;
    const int g = lane >> 2, tg = lane & 3;
    constexpr int WARP_M = (NTILE == 128) ? 2 : 4;
    constexpr int WARP_N = 8 / WARP_M;
    constexpr int MT = 128 / (WARP_M * 16);
    constexpr int NT = NTILE / (WARP_N * 8);
    const int wm = (WARP_N == 4) ? (wid >> 2) : (wid >> 1);
    const int wn = (WARP_N == 4) ? (wid & 3) : (wid & 1);

    const int m0 = blockIdx.y * 128;
    const int n0 = blockIdx.x * NTILE;
    const size_t z = blockIdx.z;
    const float* pAh = Ah + z * aZ;
    const float* pBh = Bh + z * bZ;
    const float* pAl = SPLIT ? Al + z * aZ : nullptr;
    const float* pBl = SPLIT ? Bl + z * bZ : nullptr;

    const int am = t >> 2, ak = (t & 3) << 2;
    const int bk = (NTILE == 128) ? (t >> 5) : (t >> 4);
    const int bn = (NTILE == 128) ? ((t & 31) << 2) : ((t & 15) << 2);

    float acc[MT][NT][4];
#pragma unroll
    for (int i = 0; i < MT; i++)
#pragma unroll
        for (int j = 0; j < NT; j++)
#pragma unroll
            for (int q = 0; q < 4; q++) acc[i][j][q] = 0.f;

    float4 vah[2], val_[2], vbh[2], vbl[2];

    auto cvt4 = [](float4& v) {
        v.x = to_tf32(v.x); v.y = to_tf32(v.y);
        v.z = to_tf32(v.z); v.w = to_tf32(v.w);
    };

    auto loadA = [&](int k0) {
        vah[0] = *(const float4*)(pAh + (size_t)(m0 + am) * LDA + k0 + ak);
        vah[1] = *(const float4*)(pAh + (size_t)(m0 + am + 64) * LDA + k0 + ak);
        if (RNDA) { cvt4(vah[0]); cvt4(vah[1]); }
        if constexpr (SPLIT) {
            val_[0] = *(const float4*)(pAl + (size_t)(m0 + am) * LDA + k0 + ak);
            val_[1] = *(const float4*)(pAl + (size_t)(m0 + am + 64) * LDA + k0 + ak);
        }
    };
    auto loadB = [&](int k0) {
        if constexpr (BMODE == 2) {
            vbh[0] = *(const float4*)(pBh + (size_t)(n0 + am) * LDB + k0 + ak);
            vbh[1] = *(const float4*)(pBh + (size_t)(n0 + am + 64) * LDB + k0 + ak);
            if (RNDB) { cvt4(vbh[0]); cvt4(vbh[1]); }
            if constexpr (SPLIT) {
                vbl[0] = *(const float4*)(pBl + (size_t)(n0 + am) * LDB + k0 + ak);
                vbl[1] = *(const float4*)(pBl + (size_t)(n0 + am + 64) * LDB + k0 + ak);
            }
        } else if constexpr (BMODE == 1) {
            const int n = n0 + bn;
            const size_t base = ((size_t)(n >> 6) << 16) + (size_t)(n & 63);
            vbh[0] = *(const float4*)(pBh + base + (size_t)(k0 + bk) * 64);
            vbh[1] = *(const float4*)(pBh + base + (size_t)(k0 + bk + 8) * 64);
            if (RNDB) { cvt4(vbh[0]); cvt4(vbh[1]); }
            if constexpr (SPLIT) {
                vbl[0] = *(const float4*)(pBl + base + (size_t)(k0 + bk) * 64);
                vbl[1] = *(const float4*)(pBl + base + (size_t)(k0 + bk + 8) * 64);
            }
        } else {
            vbh[0] = *(const float4*)(pBh + (size_t)(k0 + bk) * LDB + n0 + bn);
            if (NTILE == 128)
                vbh[1] = *(const float4*)(pBh + (size_t)(k0 + bk + 8) * LDB + n0 + bn);
            if (RNDB) { cvt4(vbh[0]); if (NTILE == 128) cvt4(vbh[1]); }
        }
    };
    auto stT = [&](float* dst, const float4* v) {  // transposed scalar stores
        dst[(ak + 0) * LP + am] = v[0].x;
        dst[(ak + 1) * LP + am] = v[0].y;
        dst[(ak + 2) * LP + am] = v[0].z;
        dst[(ak + 3) * LP + am] = v[0].w;
        dst[(ak + 0) * LP + am + 64] = v[1].x;
        dst[(ak + 1) * LP + am + 64] = v[1].y;
        dst[(ak + 2) * LP + am + 64] = v[1].z;
        dst[(ak + 3) * LP + am + 64] = v[1].w;
    };
    auto stageAll = [&](int buf) {
        stT(AsH + buf * BUF, vah);
        if constexpr (SPLIT) stT(AsL + buf * BUF, val_);
        if constexpr (BMODE == 2) {
            stT(BsH + buf * BUF, vbh);
            if constexpr (SPLIT) stT(BsL + buf * BUF, vbl);
        } else {
            float* d = BsH + buf * BUF;
            *(float4*)(d + bk * LP + bn) = vbh[0];
            if (NTILE == 128) *(float4*)(d + (bk + 8) * LP + bn) = vbh[1];
            if constexpr (SPLIT) {
                float* dl = BsL + buf * BUF;
                *(float4*)(dl + bk * LP + bn) = vbl[0];
                if (NTILE == 128) *(float4*)(dl + (bk + 8) * LP + bn) = vbl[1];
            }
        }
    };

    auto combo = [&](const float* Ab, const float* Bb, int kb) {
        uint32_t af[MT][4], bf[NT][2];
#pragma unroll
        for (int mt = 0; mt < MT; mt++) {
            const int m = wm * MT * 16 + mt * 16 + g;
            af[mt][0] = __float_as_uint(Ab[(kb + tg) * LP + m]);
            af[mt][1] = __float_as_uint(Ab[(kb + tg) * LP + m + 8]);
            af[mt][2] = __float_as_uint(Ab[(kb + tg + 4) * LP + m]);
            af[mt][3] = __float_as_uint(Ab[(kb + tg + 4) * LP + m + 8]);
        }
#pragma unroll
        for (int nt = 0; nt < NT; nt++) {
            const int n = wn * NT * 8 + nt * 8 + g;
            bf[nt][0] = __float_as_uint(Bb[(kb + tg) * LP + n]);
            bf[nt][1] = __float_as_uint(Bb[(kb + tg + 4) * LP + n]);
        }
#pragma unroll
        for (int mt = 0; mt < MT; mt++)
#pragma unroll
            for (int nt = 0; nt < NT; nt++) mma8(acc[mt][nt], af[mt], bf[nt]);
    };

    loadA(0);
    loadB(0);
    stageAll(0);
    __syncthreads();

    constexpr int KCH = KTOT / 16;
    int buf = 0;
#pragma unroll 1
    for (int kc = 0; kc < KCH; kc++) {
        if (kc + 1 < KCH) {
            loadA((kc + 1) * 16);
            loadB((kc + 1) * 16);
        }
        const float* abh = AsH + buf * BUF;
        const float* bbh = BsH + buf * BUF;
#pragma unroll
        for (int kk = 0; kk < 2; kk++) {
            combo(abh, bbh, kk * 8);
            if constexpr (SPLIT) {
                combo(abh, BsL + buf * BUF, kk * 8);
                combo(AsL + buf * BUF, bbh, kk * 8);
            }
        }
        if (kc + 1 < KCH) stageAll(buf ^ 1);
        __syncthreads();
        buf ^= 1;
    }

    // ---------------- epilogue ----------------
#pragma unroll
    for (int mt = 0; mt < MT; mt++) {
#pragma unroll
        for (int nt = 0; nt < NT; nt++) {
            const int r0 = m0 + wm * MT * 16 + mt * 16 + g;
            const int r1 = r0 + 8;
            const int c = n0 + wn * NT * 8 + nt * 8 + tg * 2;
            const float* a = acc[mt][nt];
            if constexpr (CMODE == 0) {
                *(float2*)(Ch + z * cZ + (size_t)r0 * LDC + c) =
                    make_float2(scale * a[0], scale * a[1]);
                *(float2*)(Ch + z * cZ + (size_t)r1 * LDC + c) =
                    make_float2(scale * a[2], scale * a[3]);
            } else {
                const size_t o0 = ((size_t)(r0 >> 10) << 20) | ((size_t)(c >> 6) << 16) |
                                  ((size_t)(r0 & 1023) << 6) | (size_t)(c & 63);
                const size_t o1 = ((size_t)(r1 >> 10) << 20) | ((size_t)(c >> 6) << 16) |
                                  ((size_t)(r1 & 1023) << 6) | (size_t)(c & 63);
                if constexpr (CMODE == 2) {
                    *(float2*)(Ch + o0) = make_float2(scale * a[0], scale * a[1]);
                    *(float2*)(Ch + o1) = make_float2(scale * a[2], scale * a[3]);
                } else {
                    float h0 = to_tf32(a[0]), h1 = to_tf32(a[1]);
                    float h2 = to_tf32(a[2]), h3 = to_tf32(a[3]);
                    *(float2*)(Ch + o0) = make_float2(h0, h1);
                    *(float2*)(Ch + o1) = make_float2(h2, h3);
                    *(float2*)(Cl + o0) =
                        make_float2(to_tf32(a[0] - h0), to_tf32(a[1] - h1));
                    *(float2*)(Cl + o1) =
                        make_float2(to_tf32(a[2] - h2), to_tf32(a[3] - h3));
                }
            }
        }
    }
}

// ============================ softmax over batch axis ============================
__global__ void softmax_b(float* __restrict__ S) {
    const size_t idx = ((size_t)blockIdx.x * 256 + threadIdx.x) * 4;
    float v[8][4];
#pragma unroll
    for (int b = 0; b < 8; b++) {
        float4 x = *(const float4*)(S + (size_t)b * 16777216u + idx);
        v[b][0] = x.x; v[b][1] = x.y; v[b][2] = x.z; v[b][3] = x.w;
    }
#pragma unroll
    for (int c = 0; c < 4; c++) {
        float mx = v[0][c];
#pragma unroll
        for (int b = 1; b < 8; b++) mx = fmaxf(mx, v[b][c]);
        float sum = 0.f;
#pragma unroll
        for (int b = 0; b < 8; b++) {
            v[b][c] = __expf(v[b][c] - mx);
            sum += v[b][c];
        }
        const float inv = 1.0f / sum;
#pragma unroll
        for (int b = 0; b < 8; b++) v[b][c] *= inv;
    }
#pragma unroll
    for (int b = 0; b < 8; b++) {
        *(float4*)(S + (size_t)b * 16777216u + idx) =
            make_float4(v[b][0], v[b][1], v[b][2], v[b][3]);
    }
}

// ============================ launcher ============================
extern "C" void kernel_launch(void* const* d_in, const int* in_sizes, int n_in,
                              void* d_out, int out_size) {
    const float* query = (const float*)d_in[0];
    const float* key_ = (const float*)d_in[1];
    const float* value = (const float*)d_in[2];
    const float* q_w = (const float*)d_in[3];
    const float* k_w = (const float*)d_in[4];
    const float* v_w = (const float*)d_in[5];
    const float* o_w = (const float*)d_in[6];
    float* out = (float*)d_out;

    float *qh, *ql, *kh, *kl, *qwh, *qwl, *kwh, *kwl;
    float *wqh, *wql, *wkh, *wkl, *wv, *sc, *hd;
    cudaGetSymbolAddress((void**)&qh, g_qh);   cudaGetSymbolAddress((void**)&ql, g_ql);
    cudaGetSymbolAddress((void**)&kh, g_kh);   cudaGetSymbolAddress((void**)&kl, g_kl);
    cudaGetSymbolAddress((void**)&qwh, g_qwh); cudaGetSymbolAddress((void**)&qwl, g_qwl);
    cudaGetSymbolAddress((void**)&kwh, g_kwh); cudaGetSymbolAddress((void**)&kwl, g_kwl);
    cudaGetSymbolAddress((void**)&wqh, g_wqh); cudaGetSymbolAddress((void**)&wql, g_wql);
    cudaGetSymbolAddress((void**)&wkh, g_wkh); cudaGetSymbolAddress((void**)&wkl, g_wkl);
    cudaGetSymbolAddress((void**)&wv, g_wv);
    cudaGetSymbolAddress((void**)&sc, g_scores);
    cudaGetSymbolAddress((void**)&hd, g_heads);

    auto kQK = mma_gemm<1024, 128, true, 1, 1, false, false, 1024, 64, 0>;
    auto kV  = mma_gemm<1024, 128, false, 1, 2, true, true, 1024, 64, 0>;
    auto kS  = mma_gemm<64, 128, true, 2, 0, false, false, 64, 64, 1024>;
    auto kPV = mma_gemm<1024, 64, false, 0, 0, true, true, 1024, 64, 64>;
    auto kO  = mma_gemm<1024, 128, false, 0, 0, true, true, 1024, 1024, 1024>;

    const int SM_SPLIT = 8 * 16 * 132 * 4;   // 67584 B
    const int SM_PLAIN = 4 * 16 * 132 * 4;   // 33792 B
    cudaFuncSetAttribute((const void*)kQK, cudaFuncAttributeMaxDynamicSharedMemorySize, SM_SPLIT);
    cudaFuncSetAttribute((const void*)kV,  cudaFuncAttributeMaxDynamicSharedMemorySize, SM_PLAIN);
    cudaFuncSetAttribute((const void*)kS,  cudaFuncAttributeMaxDynamicSharedMemorySize, SM_SPLIT);
    cudaFuncSetAttribute((const void*)kPV, cudaFuncAttributeMaxDynamicSharedMemorySize, SM_PLAIN);
    cudaFuncSetAttribute((const void*)kO,  cudaFuncAttributeMaxDynamicSharedMemorySize, SM_PLAIN);

    // 1) hi/lo splits of score-path inputs
    split_k<<<8192, 256>>>(query, qh, ql);
    split_k<<<8192, 256>>>(key_, kh, kl);
    split_k<<<1024, 256>>>(q_w, qwh, qwl);
    split_k<<<1024, 256>>>(k_w, kwh, kwl);

    // 2) Q/K projections (3xtf32) -> split [b,h,i,s]
    kQK<<<dim3(8, 64, 1), 256, SM_SPLIT>>>(qh, ql, qwh, qwl, wqh, wql, 0, 0, 0, 1.0f);
    kQK<<<dim3(8, 64, 1), 256, SM_SPLIT>>>(kh, kl, kwh, kwl, wkh, wkl, 0, 0, 0, 1.0f);

    // 3) V projection (1xtf32) -> [b,h,j,s]
    kV<<<dim3(8, 64, 1), 256, SM_PLAIN>>>(value, nullptr, v_w, nullptr, wv, nullptr,
                                          0, 0, 0, 1.0f);

    // 4) scores = 0.25 * WQ WK^T per (b,h), 3xtf32
    kS<<<dim3(8, 8, 128), 256, SM_SPLIT>>>(wqh, wql, wkh, wkl, sc, nullptr,
                                           65536, 65536, 1048576, 0.25f);

    // 5) softmax over batch axis
    softmax_b<<<16384, 256>>>(sc);

    // 6) heads = P * WV per (b,h) -> [b,h,i,s]
    kPV<<<dim3(1, 8, 128), 256, SM_PLAIN>>>(sc, nullptr, wv, nullptr, hd, nullptr,
                                            1048576, 65536, 65536, 1.0f);

    // 7) out = heads_flat x o_w
    kO<<<dim3(8, 64, 1), 256, SM_PLAIN>>>(hd, nullptr, o_w, nullptr, out, nullptr,
                                          0, 0, 0, 1.0f);
}